// round 1
// baseline (speedup 1.0000x reference)
#include <cuda_runtime.h>
#include <math.h>

// ---------------- problem dims ----------------
#define Bq 16
#define Lq 196
#define FDq 2048
#define Nq 1000
#define WDq 300
#define HDq 512
#define DDq 5
#define NIMGq 1000
#define TMAXq 5

// ---------------- device scratch (no allocations allowed) ----------------
__device__ float g_keysfk[3136 * 1024];   // [B*L, 1024]: cols 0..511 keys, 512..1023 FK=feats@Wf1
__device__ float g_WB[2048 * 1024];       // packed [W_key | Wf1]
__device__ float g_biasB[1024];           // [b_key | 0]
__device__ float g_queries[1000 * 512];
__device__ float g_kT[16 * 512 * 196];    // keys transposed per b: [b][h][l]
__device__ float g_scores[16 * 1000 * 196];
__device__ float g_H1[16000 * 512];
__device__ float g_P[1000 * 256];
__device__ float g_Qm[1000 * 256];
__device__ float g_prop[1000 * 1000];
__device__ float g_hA[16000 * 5];
__device__ float g_hB[16000 * 5];
__device__ float g_msg[16000 * 5];
__device__ float g_pooled[16 * 2048];

// ---------------- generic tiled SGEMM: C = A*B (+bias) (+relu), batched via z ----------------
__global__ __launch_bounds__(256) void sgemm128(
    const float* __restrict__ A, int lda, long long sA,
    const float* __restrict__ B, int ldb, long long sB,
    const float* __restrict__ bias,
    float* __restrict__ C, int ldc, long long sC,
    int M, int N, int K, int do_relu)
{
    __shared__ float As[8][128];
    __shared__ float Bs[8][128];
    int z = blockIdx.z;
    A += (size_t)z * sA; B += (size_t)z * sB; C += (size_t)z * sC;
    int tid = threadIdx.x;
    int brow = blockIdx.y * 128;
    int bcol = blockIdx.x * 128;
    int arow = tid >> 1;
    int acol = (tid & 1) * 4;
    int bkrow = tid >> 5;
    int bncol = (tid & 31) * 4;
    int ty = tid >> 4, tx = tid & 15;

    float acc[8][8];
#pragma unroll
    for (int i = 0; i < 8; i++)
#pragma unroll
        for (int j = 0; j < 8; j++) acc[i][j] = 0.f;

    for (int k0 = 0; k0 < K; k0 += 8) {
        float4 av = make_float4(0.f, 0.f, 0.f, 0.f);
        if (brow + arow < M && k0 + acol < K)
            av = *reinterpret_cast<const float4*>(A + (size_t)(brow + arow) * lda + k0 + acol);
        As[acol + 0][arow] = av.x; As[acol + 1][arow] = av.y;
        As[acol + 2][arow] = av.z; As[acol + 3][arow] = av.w;

        float4 bv = make_float4(0.f, 0.f, 0.f, 0.f);
        if (k0 + bkrow < K && bcol + bncol < N)
            bv = *reinterpret_cast<const float4*>(B + (size_t)(k0 + bkrow) * ldb + bcol + bncol);
        *reinterpret_cast<float4*>(&Bs[bkrow][bncol]) = bv;
        __syncthreads();

#pragma unroll
        for (int kk = 0; kk < 8; kk++) {
            float4 a0 = *reinterpret_cast<const float4*>(&As[kk][ty * 8]);
            float4 a1 = *reinterpret_cast<const float4*>(&As[kk][ty * 8 + 4]);
            float4 b0 = *reinterpret_cast<const float4*>(&Bs[kk][tx * 8]);
            float4 b1 = *reinterpret_cast<const float4*>(&Bs[kk][tx * 8 + 4]);
            float ar[8] = {a0.x, a0.y, a0.z, a0.w, a1.x, a1.y, a1.z, a1.w};
            float br[8] = {b0.x, b0.y, b0.z, b0.w, b1.x, b1.y, b1.z, b1.w};
#pragma unroll
            for (int i = 0; i < 8; i++)
#pragma unroll
                for (int j = 0; j < 8; j++)
                    acc[i][j] = fmaf(ar[i], br[j], acc[i][j]);
        }
        __syncthreads();
    }

#pragma unroll
    for (int i = 0; i < 8; i++) {
        int r = brow + ty * 8 + i;
        if (r >= M) continue;
#pragma unroll
        for (int j = 0; j < 8; j++) {
            int c = bcol + tx * 8 + j;
            if (c >= N) continue;
            float v = acc[i][j];
            if (bias) v += bias[c];
            if (do_relu) v = fmaxf(v, 0.f);
            C[(size_t)r * ldc + c] = v;
        }
    }
}

// ---------------- small kernels ----------------
__global__ void pooled_kernel(const float* __restrict__ feats) {
    int f = blockIdx.x * 256 + threadIdx.x;   // 0..2047
    int b = blockIdx.y;
    const float* p = feats + (size_t)b * Lq * FDq + f;
    float s = 0.f;
#pragma unroll 4
    for (int l = 0; l < Lq; l++) s += p[(size_t)l * FDq];
    g_pooled[b * FDq + f] = s * (1.f / (float)Lq);
}

__global__ void clf_kernel(const float* __restrict__ W_clf, const float* __restrict__ b_clf,
                           float* __restrict__ out_img) {
    __shared__ float sp[2048];
    int b = blockIdx.y;
    for (int i = threadIdx.x; i < 2048; i += 128) sp[i] = g_pooled[b * 2048 + i];
    __syncthreads();
    int c = blockIdx.x * 128 + threadIdx.x;
    if (c >= NIMGq) return;
    float acc = b_clf[c];
#pragma unroll 8
    for (int f = 0; f < 2048; f++) acc = fmaf(sp[f], W_clf[(size_t)f * NIMGq + c], acc);
    out_img[b * NIMGq + c] = acc;
}

__global__ void softmax1000(float* __restrict__ base) {
    __shared__ float sv[1000];
    __shared__ float red[8];
    int b = blockIdx.x, tid = threadIdx.x;
    float* row = base + (size_t)b * 1000;
    float m = -1e30f;
    for (int i = tid; i < 1000; i += 256) { float x = row[i]; sv[i] = x; m = fmaxf(m, x); }
    for (int o = 16; o; o >>= 1) m = fmaxf(m, __shfl_xor_sync(0xffffffffu, m, o));
    if ((tid & 31) == 0) red[tid >> 5] = m;
    __syncthreads();
    float bm = red[0];
#pragma unroll
    for (int i = 1; i < 8; i++) bm = fmaxf(bm, red[i]);
    float s = 0.f;
    for (int i = tid; i < 1000; i += 256) { float e = expf(sv[i] - bm); sv[i] = e; s += e; }
    for (int o = 16; o; o >>= 1) s += __shfl_xor_sync(0xffffffffu, s, o);
    __syncthreads();
    if ((tid & 31) == 0) red[tid >> 5] = s;
    __syncthreads();
    float bs = 0.f;
#pragma unroll
    for (int i = 0; i < 8; i++) bs += red[i];
    float inv = 1.f / bs;
    for (int i = tid; i < 1000; i += 256) row[i] = sv[i] * inv;
}

__global__ void packB(const float* __restrict__ Wk, const float* __restrict__ bk,
                      const float* __restrict__ Wf1) {
    int idx = blockIdx.x * 256 + threadIdx.x;
    if (idx < 2048 * 1024) {
        int k = idx >> 10, j = idx & 1023;
        g_WB[idx] = (j < 512) ? Wk[k * 512 + j] : Wf1[k * 512 + j - 512];
    }
    if (idx < 1024) g_biasB[idx] = (idx < 512) ? bk[idx] : 0.f;
}

// transpose keys (cols 0..511 of g_keysfk) into g_kT[b][h][l]
__global__ void transpose_keys() {
    __shared__ float tile[32][33];
    int b = blockIdx.z;
    int l0 = blockIdx.x * 32, h0 = blockIdx.y * 32;
    int tx = threadIdx.x, ty = threadIdx.y;   // blockDim (32,8)
#pragma unroll
    for (int i = 0; i < 32; i += 8) {
        int l = l0 + i + ty;
        tile[i + ty][tx] = (l < Lq) ? g_keysfk[((size_t)b * Lq + l) * 1024 + h0 + tx] : 0.f;
    }
    __syncthreads();
#pragma unroll
    for (int i = 0; i < 32; i += 8) {
        int h = h0 + i + ty;
        int l = l0 + tx;
        if (l < Lq) g_kT[((size_t)b * 512 + h) * Lq + l] = tile[tx][i + ty];
    }
}

// warp-per-row softmax over 196 (scores -> attn in d_out)
__global__ void softmax196(float* __restrict__ attn) {
    int gw = (blockIdx.x * blockDim.x + threadIdx.x) >> 5;
    int lane = threadIdx.x & 31;
    if (gw >= Bq * Nq) return;
    const float* src = g_scores + (size_t)gw * Lq;
    float v[7];
    float m = -1e30f;
#pragma unroll
    for (int i = 0; i < 7; i++) {
        int j = lane + 32 * i;
        v[i] = (j < Lq) ? src[j] : -1e30f;
        m = fmaxf(m, v[i]);
    }
    for (int o = 16; o; o >>= 1) m = fmaxf(m, __shfl_xor_sync(0xffffffffu, m, o));
    float s = 0.f;
#pragma unroll
    for (int i = 0; i < 7; i++) {
        int j = lane + 32 * i;
        v[i] = (j < Lq) ? expf(v[i] - m) : 0.f;
        s += v[i];
    }
    for (int o = 16; o; o >>= 1) s += __shfl_xor_sync(0xffffffffu, s, o);
    float inv = 1.f / s;
#pragma unroll
    for (int i = 0; i < 7; i++) {
        int j = lane + 32 * i;
        if (j < Lq) attn[(size_t)gw * Lq + j] = v[i] * inv;
    }
}

// h0 = H1 @ Wf2 + bf2 -> g_hA   (warp per row)
__global__ void h0_kernel(const float* __restrict__ Wf2, const float* __restrict__ bf2) {
    int gw = (blockIdx.x * blockDim.x + threadIdx.x) >> 5;
    int lane = threadIdx.x & 31;
    if (gw >= 16000) return;
    const float* row = g_H1 + (size_t)gw * 512;
    float acc[5] = {0.f, 0.f, 0.f, 0.f, 0.f};
#pragma unroll
    for (int i = 0; i < 16; i++) {
        int j = lane + 32 * i;
        float v = row[j];
#pragma unroll
        for (int d = 0; d < 5; d++) acc[d] = fmaf(v, Wf2[j * 5 + d], acc[d]);
    }
#pragma unroll
    for (int d = 0; d < 5; d++)
        for (int o = 16; o; o >>= 1) acc[d] += __shfl_xor_sync(0xffffffffu, acc[d], o);
    if (lane == 0) {
#pragma unroll
        for (int d = 0; d < 5; d++) g_hA[gw * 5 + d] = acc[d] + bf2[d];
    }
}

__global__ void zero_prop() {
    int i = blockIdx.x * 256 + threadIdx.x;
    if (i < 1000 * 1000) g_prop[i] = 0.f;
}

// edge: val = tanh( relu(P[s]+Qm[d]+br1) . Wr2 + br2 ), scatter-add to prop[s,d]
__global__ void edge_kernel(const int* __restrict__ edges, const float* __restrict__ br1,
                            const float* __restrict__ Wr2, const float* __restrict__ br2, int E) {
    int e = blockIdx.x * 8 + (threadIdx.x >> 5);
    int lane = threadIdx.x & 31;
    if (e >= E) return;
    int s = edges[e];
    int d = edges[E + e];
    const float* Pr = g_P + (size_t)s * 256;
    const float* Qr = g_Qm + (size_t)d * 256;
    float acc = 0.f;
#pragma unroll
    for (int i = 0; i < 8; i++) {
        int j = lane + 32 * i;
        float h = fmaxf(Pr[j] + Qr[j] + br1[j], 0.f);
        acc = fmaf(h, Wr2[j], acc);
    }
    for (int o = 16; o; o >>= 1) acc += __shfl_xor_sync(0xffffffffu, acc, o);
    if (lane == 0) atomicAdd(&g_prop[(size_t)s * 1000 + d], tanhf(acc + br2[0]));
}

// msg[b,n,:] = tanh( sum_m prop[n,m] * hin[b,m,:] )   (320 threads: 64 n x 5 d)
__global__ void msg_kernel(int sel) {
    __shared__ float sp[64][65];
    __shared__ float sh[320];
    const float* hin = sel ? g_hB : g_hA;
    int b = blockIdx.y;
    int n0 = blockIdx.x * 64;
    int tid = threadIdx.x;
    int nl = tid / 5, d = tid % 5;
    float acc = 0.f;
    for (int m0 = 0; m0 < 1000; m0 += 64) {
        int mlen = min(64, 1000 - m0);
        for (int idx = tid; idx < 64 * 64; idx += 320) {
            int r = idx >> 6, c = idx & 63;
            sp[r][c] = (n0 + r < 1000 && c < mlen) ? g_prop[(size_t)(n0 + r) * 1000 + m0 + c] : 0.f;
        }
        sh[tid] = (tid < mlen * 5) ? hin[((size_t)b * 1000 + m0) * 5 + tid] : 0.f;
        __syncthreads();
#pragma unroll 8
        for (int mm = 0; mm < 64; mm++)
            acc = fmaf(sp[nl][mm], sh[mm * 5 + d], acc);
        __syncthreads();
    }
    if (n0 + nl < 1000) g_msg[((size_t)b * 1000 + n0 + nl) * 5 + d] = tanhf(acc);
}

__global__ void gru_kernel(const float* __restrict__ Wih, const float* __restrict__ bih,
                           const float* __restrict__ Whh, const float* __restrict__ bhh, int sel) {
    int r = blockIdx.x * 256 + threadIdx.x;
    if (r >= 16000) return;
    const float* hin = sel ? g_hB : g_hA;
    float* hout = sel ? g_hA : g_hB;
    float x[5], h[5];
#pragma unroll
    for (int d = 0; d < 5; d++) { x[d] = g_msg[r * 5 + d]; h[d] = hin[r * 5 + d]; }
    float out[5];
#pragma unroll
    for (int d = 0; d < 5; d++) {
        float ir = bih[d], iz = bih[5 + d], in = bih[10 + d];
        float hr = bhh[d], hz = bhh[5 + d], hn = bhh[10 + d];
#pragma unroll
        for (int k = 0; k < 5; k++) {
            ir = fmaf(x[k], Wih[d * 5 + k], ir);
            iz = fmaf(x[k], Wih[(5 + d) * 5 + k], iz);
            in = fmaf(x[k], Wih[(10 + d) * 5 + k], in);
            hr = fmaf(h[k], Whh[d * 5 + k], hr);
            hz = fmaf(h[k], Whh[(5 + d) * 5 + k], hz);
            hn = fmaf(h[k], Whh[(10 + d) * 5 + k], hn);
        }
        float rr = 1.f / (1.f + expf(-(ir + hr)));
        float zz = 1.f / (1.f + expf(-(iz + hz)));
        float nn = tanhf(in + rr * hn);
        out[d] = (1.f - zz) * nn + zz * h[d];
    }
#pragma unroll
    for (int d = 0; d < 5; d++) hout[r * 5 + d] = out[d];
}

// logits = relu(h @ Wo1 + bo1) @ Wo2 + bo2  (warp per row, reads g_hB)
__global__ void out_kernel(const float* __restrict__ Wo1, const float* __restrict__ bo1,
                           const float* __restrict__ Wo2, const float* __restrict__ bo2,
                           float* __restrict__ out) {
    int gw = (blockIdx.x * blockDim.x + threadIdx.x) >> 5;
    int lane = threadIdx.x & 31;
    if (gw >= 16000) return;
    float h[5];
#pragma unroll
    for (int d = 0; d < 5; d++) h[d] = g_hB[gw * 5 + d];
    float acc = 0.f;
#pragma unroll
    for (int i = 0; i < 16; i++) {
        int j = lane + 32 * i;
        float t = bo1[j];
#pragma unroll
        for (int d = 0; d < 5; d++) t = fmaf(h[d], Wo1[d * 512 + j], t);
        acc = fmaf(fmaxf(t, 0.f), Wo2[j], acc);
    }
    for (int o = 16; o; o >>= 1) acc += __shfl_xor_sync(0xffffffffu, acc, o);
    if (lane == 0) out[gw] = acc + bo2[0];
}

// ---------------- launcher ----------------
extern "C" void kernel_launch(void* const* d_in, const int* in_sizes, int n_in,
                              void* d_out, int out_size) {
    const float* feats  = (const float*)d_in[0];
    const float* embed  = (const float*)d_in[1];
    const int*   edges  = (const int*)d_in[2];
    const float* W_key  = (const float*)d_in[3];
    const float* b_key  = (const float*)d_in[4];
    const float* W_query= (const float*)d_in[5];
    const float* b_query= (const float*)d_in[6];
    const float* Wf1    = (const float*)d_in[7];
    const float* bf1    = (const float*)d_in[8];
    const float* Wf2    = (const float*)d_in[9];
    const float* bf2    = (const float*)d_in[10];
    const float* Wr1    = (const float*)d_in[11];
    const float* br1    = (const float*)d_in[12];
    const float* Wr2    = (const float*)d_in[13];
    const float* br2    = (const float*)d_in[14];
    const float* Wo1    = (const float*)d_in[15];
    const float* bo1    = (const float*)d_in[16];
    const float* Wo2    = (const float*)d_in[17];
    const float* bo2    = (const float*)d_in[18];
    const float* W_ih   = (const float*)d_in[19];
    const float* b_ih   = (const float*)d_in[20];
    const float* W_hh   = (const float*)d_in[21];
    const float* b_hh   = (const float*)d_in[22];
    const float* W_clf  = (const float*)d_in[23];
    const float* b_clf  = (const float*)d_in[24];

    float* out        = (float*)d_out;
    float* out_logits = out;                       // [16,1000]
    float* out_attn   = out + 16000;               // [16,1000,196]
    float* out_img    = out + 16000 + 16 * 1000 * 196;  // [16,1000]

    int E = in_sizes[2] / 2;

    // device scratch addresses (host-side symbol lookups; no allocation, capture-safe)
    float *p_keysfk, *p_WB, *p_biasB, *p_queries, *p_kT, *p_scores, *p_H1, *p_P, *p_Qm;
    cudaGetSymbolAddress((void**)&p_keysfk, g_keysfk);
    cudaGetSymbolAddress((void**)&p_WB, g_WB);
    cudaGetSymbolAddress((void**)&p_biasB, g_biasB);
    cudaGetSymbolAddress((void**)&p_queries, g_queries);
    cudaGetSymbolAddress((void**)&p_kT, g_kT);
    cudaGetSymbolAddress((void**)&p_scores, g_scores);
    cudaGetSymbolAddress((void**)&p_H1, g_H1);
    cudaGetSymbolAddress((void**)&p_P, g_P);
    cudaGetSymbolAddress((void**)&p_Qm, g_Qm);

    // ---- imagenet branch ----
    pooled_kernel<<<dim3(8, 16), 256>>>(feats);
    clf_kernel<<<dim3(8, 16), 128>>>(W_clf, b_clf, out_img);
    softmax1000<<<16, 256>>>(out_img);

    // ---- fused feats GEMM: [keys | FK] = feats @ [W_key | Wf1] (+[b_key|0]) ----
    packB<<<8192, 256>>>(W_key, b_key, Wf1);
    sgemm128<<<dim3(8, 25, 1), 256>>>(feats, 2048, 0, p_WB, 1024, 0, p_biasB,
                                      p_keysfk, 1024, 0, 3136, 1024, 2048, 0);

    // ---- queries = embed @ W_query + b_query ----
    sgemm128<<<dim3(4, 8, 1), 256>>>(embed, 300, 0, W_query, 512, 0, b_query,
                                     p_queries, 512, 0, 1000, 512, 300, 0);

    // ---- scores = queries @ keys^T (per b), via kT ----
    transpose_keys<<<dim3(7, 16, 16), dim3(32, 8)>>>();
    sgemm128<<<dim3(2, 8, 16), 256>>>(p_queries, 512, 0, p_kT, 196, (long long)512 * 196,
                                      nullptr, p_scores, 196, (long long)1000 * 196,
                                      1000, 196, 512, 0);
    softmax196<<<2000, 256>>>(out_attn);

    // ---- hidden1 = relu(attn @ FK + bf1); h0 = hidden1 @ Wf2 + bf2 ----
    sgemm128<<<dim3(4, 8, 16), 256>>>(out_attn, 196, (long long)1000 * 196,
                                      p_keysfk + 512, 1024, (long long)196 * 1024, bf1,
                                      p_H1, 512, (long long)1000 * 512,
                                      1000, 512, 196, 1);
    h0_kernel<<<2000, 256>>>(Wf2, bf2);

    // ---- edge weights: P/Qm precompute + per-edge finish + scatter ----
    sgemm128<<<dim3(2, 8, 1), 256>>>(embed, 300, 0, Wr1, 256, 0, nullptr,
                                     p_P, 256, 0, 1000, 256, 300, 0);
    sgemm128<<<dim3(2, 8, 1), 256>>>(embed, 300, 0, Wr1 + 300 * 256, 256, 0, nullptr,
                                     p_Qm, 256, 0, 1000, 256, 300, 0);
    zero_prop<<<3907, 256>>>();
    edge_kernel<<<(E + 7) / 8, 256>>>(edges, br1, Wr2, br2, E);

    // ---- 5 message-passing + GRU steps (ping-pong g_hA/g_hB) ----
    for (int t = 0; t < TMAXq; t++) {
        int sel = t & 1;   // 0: read hA write hB ; 1: read hB write hA
        msg_kernel<<<dim3(16, 16), 320>>>(sel);
        gru_kernel<<<63, 256>>>(W_ih, b_ih, W_hh, b_hh, sel);
    }

    // final hidden lives in g_hB after 5 steps
    out_kernel<<<2000, 256>>>(Wo1, bo1, Wo2, bo2, out_logits);

    (void)n_in; (void)out_size;
}

// round 2
// speedup vs baseline: 1.1010x; 1.1010x over previous
#include <cuda_runtime.h>
#include <math.h>

// ---------------- problem dims ----------------
#define Bq 16
#define Lq 196
#define FDq 2048
#define Nq 1000
#define WDq 300
#define HDq 512
#define DDq 5
#define NIMGq 1000
#define TMAXq 5

// ---------------- device scratch (no allocations allowed) ----------------
__device__ __align__(256) float g_keysfk[3136 * 1024];   // [B*L, 1024]: cols 0..511 keys, 512..1023 FK
__device__ __align__(256) float g_WB[2048 * 1024];       // packed [W_key | Wf1]
__device__ __align__(256) float g_biasB[1024];           // [b_key | 0]
__device__ __align__(256) float g_queries[1000 * 512];
__device__ __align__(256) float g_kT[16 * 512 * 196];    // keys transposed per b: [b][h][l]
__device__ __align__(256) float g_scores[16 * 1000 * 196];
__device__ __align__(256) float g_H1[16000 * 512];
__device__ __align__(256) float g_P[1000 * 256];
__device__ __align__(256) float g_Qm[1000 * 256];
__device__ __align__(256) float g_prop[1000 * 1000];
__device__ __align__(256) float g_hA[16000 * 5];
__device__ __align__(256) float g_hB[16000 * 5];
__device__ __align__(256) float g_msg[16000 * 5];
__device__ __align__(256) float g_pooled[16 * 2048];

// ---------------- double-buffered tiled SGEMM: C = A*B (+bias)(+relu), batched via z ----
// 128x128 tile, BK=16, 256 threads, 8x8 microtile, reg-prefetch + smem double buffer.
// Requires K % 4 == 0 (true for all call sites: 2048, 512, 300, 196).
__global__ __launch_bounds__(256, 2) void sgemm_db(
    const float* __restrict__ A, int lda, long long sA,
    const float* __restrict__ B, int ldb, long long sB,
    const float* __restrict__ bias,
    float* __restrict__ C, int ldc, long long sC,
    int M, int N, int K, int do_relu)
{
    __shared__ float As[2][16][128];
    __shared__ float Bs[2][16][128];
    int z = blockIdx.z;
    A += (size_t)z * sA; B += (size_t)z * sB; C += (size_t)z * sC;
    int tid = threadIdx.x;
    int brow = blockIdx.y * 128;
    int bcol = blockIdx.x * 128;

    // A tile load mapping: each thread loads 8 floats (2 x float4) of one row
    int a_row = tid >> 1;              // 0..127
    int a_col = (tid & 1) * 8;         // 0 or 8
    // B tile load mapping: each thread loads 8 floats (2 x float4) of one k-row
    int b_k   = tid >> 4;              // 0..15
    int b_col = (tid & 15) * 8;        // 0..120

    int ty = tid >> 4, tx = tid & 15;

    float acc[8][8];
#pragma unroll
    for (int i = 0; i < 8; i++)
#pragma unroll
        for (int j = 0; j < 8; j++) acc[i][j] = 0.f;

    int nk = (K + 15) >> 4;

    float4 pa0, pa1, pb0, pb1;

    // ---- preload tile 0 into regs ----
    {
        int k0 = 0;
        pa0 = make_float4(0.f,0.f,0.f,0.f); pa1 = pa0; pb0 = pa0; pb1 = pa0;
        if (brow + a_row < M) {
            const float* p = A + (size_t)(brow + a_row) * lda + k0 + a_col;
            if (k0 + a_col < K)     pa0 = *reinterpret_cast<const float4*>(p);
            if (k0 + a_col + 4 < K) pa1 = *reinterpret_cast<const float4*>(p + 4);
        }
        if (k0 + b_k < K) {
            const float* p = B + (size_t)(k0 + b_k) * ldb + bcol + b_col;
            if (bcol + b_col < N)     pb0 = *reinterpret_cast<const float4*>(p);
            if (bcol + b_col + 4 < N) pb1 = *reinterpret_cast<const float4*>(p + 4);
        }
    }
    // store tile 0 to buffer 0
    {
        As[0][a_col+0][a_row] = pa0.x; As[0][a_col+1][a_row] = pa0.y;
        As[0][a_col+2][a_row] = pa0.z; As[0][a_col+3][a_row] = pa0.w;
        As[0][a_col+4][a_row] = pa1.x; As[0][a_col+5][a_row] = pa1.y;
        As[0][a_col+6][a_row] = pa1.z; As[0][a_col+7][a_row] = pa1.w;
        *reinterpret_cast<float4*>(&Bs[0][b_k][b_col])     = pb0;
        *reinterpret_cast<float4*>(&Bs[0][b_k][b_col + 4]) = pb1;
    }
    __syncthreads();

    for (int t = 0; t < nk; t++) {
        int buf = t & 1;
        int nxt = t + 1;
        if (nxt < nk) {
            int k0 = nxt << 4;
            pa0 = make_float4(0.f,0.f,0.f,0.f); pa1 = pa0; pb0 = pa0; pb1 = pa0;
            if (brow + a_row < M) {
                const float* p = A + (size_t)(brow + a_row) * lda + k0 + a_col;
                if (k0 + a_col < K)     pa0 = *reinterpret_cast<const float4*>(p);
                if (k0 + a_col + 4 < K) pa1 = *reinterpret_cast<const float4*>(p + 4);
            }
            if (k0 + b_k < K) {
                const float* p = B + (size_t)(k0 + b_k) * ldb + bcol + b_col;
                if (bcol + b_col < N)     pb0 = *reinterpret_cast<const float4*>(p);
                if (bcol + b_col + 4 < N) pb1 = *reinterpret_cast<const float4*>(p + 4);
            }
        }

#pragma unroll
        for (int kk = 0; kk < 16; kk++) {
            float4 a0 = *reinterpret_cast<const float4*>(&As[buf][kk][ty * 8]);
            float4 a1 = *reinterpret_cast<const float4*>(&As[buf][kk][ty * 8 + 4]);
            float4 b0 = *reinterpret_cast<const float4*>(&Bs[buf][kk][tx * 8]);
            float4 b1 = *reinterpret_cast<const float4*>(&Bs[buf][kk][tx * 8 + 4]);
            float ar[8] = {a0.x, a0.y, a0.z, a0.w, a1.x, a1.y, a1.z, a1.w};
            float br[8] = {b0.x, b0.y, b0.z, b0.w, b1.x, b1.y, b1.z, b1.w};
#pragma unroll
            for (int i = 0; i < 8; i++)
#pragma unroll
                for (int j = 0; j < 8; j++)
                    acc[i][j] = fmaf(ar[i], br[j], acc[i][j]);
        }

        if (nxt < nk) {
            int nb = nxt & 1;
            As[nb][a_col+0][a_row] = pa0.x; As[nb][a_col+1][a_row] = pa0.y;
            As[nb][a_col+2][a_row] = pa0.z; As[nb][a_col+3][a_row] = pa0.w;
            As[nb][a_col+4][a_row] = pa1.x; As[nb][a_col+5][a_row] = pa1.y;
            As[nb][a_col+6][a_row] = pa1.z; As[nb][a_col+7][a_row] = pa1.w;
            *reinterpret_cast<float4*>(&Bs[nb][b_k][b_col])     = pb0;
            *reinterpret_cast<float4*>(&Bs[nb][b_k][b_col + 4]) = pb1;
        }
        __syncthreads();
    }

#pragma unroll
    for (int i = 0; i < 8; i++) {
        int r = brow + ty * 8 + i;
        if (r >= M) continue;
#pragma unroll
        for (int j = 0; j < 8; j++) {
            int c = bcol + tx * 8 + j;
            if (c >= N) continue;
            float v = acc[i][j];
            if (bias) v += bias[c];
            if (do_relu) v = fmaxf(v, 0.f);
            C[(size_t)r * ldc + c] = v;
        }
    }
}

// ---------------- small kernels ----------------
__global__ void pooled_kernel(const float* __restrict__ feats) {
    int f = blockIdx.x * 256 + threadIdx.x;   // 0..2047
    int b = blockIdx.y;
    const float* p = feats + (size_t)b * Lq * FDq + f;
    float s = 0.f;
#pragma unroll 4
    for (int l = 0; l < Lq; l++) s += p[(size_t)l * FDq];
    g_pooled[b * FDq + f] = s * (1.f / (float)Lq);
}

__global__ void clf_kernel(const float* __restrict__ W_clf, const float* __restrict__ b_clf,
                           float* __restrict__ out_img) {
    __shared__ float sp[2048];
    int b = blockIdx.y;
    for (int i = threadIdx.x; i < 2048; i += 128) sp[i] = g_pooled[b * 2048 + i];
    __syncthreads();
    int c = blockIdx.x * 128 + threadIdx.x;
    if (c >= NIMGq) return;
    float acc = b_clf[c];
#pragma unroll 8
    for (int f = 0; f < 2048; f++) acc = fmaf(sp[f], W_clf[(size_t)f * NIMGq + c], acc);
    out_img[b * NIMGq + c] = acc;
}

__global__ void softmax1000(float* __restrict__ base) {
    __shared__ float sv[1000];
    __shared__ float red[8];
    int b = blockIdx.x, tid = threadIdx.x;
    float* row = base + (size_t)b * 1000;
    float m = -1e30f;
    for (int i = tid; i < 1000; i += 256) { float x = row[i]; sv[i] = x; m = fmaxf(m, x); }
    for (int o = 16; o; o >>= 1) m = fmaxf(m, __shfl_xor_sync(0xffffffffu, m, o));
    if ((tid & 31) == 0) red[tid >> 5] = m;
    __syncthreads();
    float bm = red[0];
#pragma unroll
    for (int i = 1; i < 8; i++) bm = fmaxf(bm, red[i]);
    float s = 0.f;
    for (int i = tid; i < 1000; i += 256) { float e = expf(sv[i] - bm); sv[i] = e; s += e; }
    for (int o = 16; o; o >>= 1) s += __shfl_xor_sync(0xffffffffu, s, o);
    __syncthreads();
    if ((tid & 31) == 0) red[tid >> 5] = s;
    __syncthreads();
    float bs = 0.f;
#pragma unroll
    for (int i = 0; i < 8; i++) bs += red[i];
    float inv = 1.f / bs;
    for (int i = tid; i < 1000; i += 256) row[i] = sv[i] * inv;
}

__global__ void packB(const float* __restrict__ Wk, const float* __restrict__ bk,
                      const float* __restrict__ Wf1) {
    int idx = blockIdx.x * 256 + threadIdx.x;
    if (idx < 2048 * 1024) {
        int k = idx >> 10, j = idx & 1023;
        g_WB[idx] = (j < 512) ? Wk[k * 512 + j] : Wf1[k * 512 + j - 512];
    }
    if (idx < 1024) g_biasB[idx] = (idx < 512) ? bk[idx] : 0.f;
}

// transpose keys (cols 0..511 of g_keysfk) into g_kT[b][h][l]
__global__ void transpose_keys() {
    __shared__ float tile[32][33];
    int b = blockIdx.z;
    int l0 = blockIdx.x * 32, h0 = blockIdx.y * 32;
    int tx = threadIdx.x, ty = threadIdx.y;   // blockDim (32,8)
#pragma unroll
    for (int i = 0; i < 32; i += 8) {
        int l = l0 + i + ty;
        tile[i + ty][tx] = (l < Lq) ? g_keysfk[((size_t)b * Lq + l) * 1024 + h0 + tx] : 0.f;
    }
    __syncthreads();
#pragma unroll
    for (int i = 0; i < 32; i += 8) {
        int h = h0 + i + ty;
        int l = l0 + tx;
        if (l < Lq) g_kT[((size_t)b * 512 + h) * Lq + l] = tile[tx][i + ty];
    }
}

// warp-per-row softmax over 196 (scores -> attn in d_out)
__global__ void softmax196(float* __restrict__ attn) {
    int gw = (blockIdx.x * blockDim.x + threadIdx.x) >> 5;
    int lane = threadIdx.x & 31;
    if (gw >= Bq * Nq) return;
    const float* src = g_scores + (size_t)gw * Lq;
    float v[7];
    float m = -1e30f;
#pragma unroll
    for (int i = 0; i < 7; i++) {
        int j = lane + 32 * i;
        v[i] = (j < Lq) ? src[j] : -1e30f;
        m = fmaxf(m, v[i]);
    }
    for (int o = 16; o; o >>= 1) m = fmaxf(m, __shfl_xor_sync(0xffffffffu, m, o));
    float s = 0.f;
#pragma unroll
    for (int i = 0; i < 7; i++) {
        int j = lane + 32 * i;
        v[i] = (j < Lq) ? expf(v[i] - m) : 0.f;
        s += v[i];
    }
    for (int o = 16; o; o >>= 1) s += __shfl_xor_sync(0xffffffffu, s, o);
    float inv = 1.f / s;
#pragma unroll
    for (int i = 0; i < 7; i++) {
        int j = lane + 32 * i;
        if (j < Lq) attn[(size_t)gw * Lq + j] = v[i] * inv;
    }
}

// h0 = H1 @ Wf2 + bf2 -> g_hA   (warp per row)
__global__ void h0_kernel(const float* __restrict__ Wf2, const float* __restrict__ bf2) {
    int gw = (blockIdx.x * blockDim.x + threadIdx.x) >> 5;
    int lane = threadIdx.x & 31;
    if (gw >= 16000) return;
    const float* row = g_H1 + (size_t)gw * 512;
    float acc[5] = {0.f, 0.f, 0.f, 0.f, 0.f};
#pragma unroll
    for (int i = 0; i < 16; i++) {
        int j = lane + 32 * i;
        float v = row[j];
#pragma unroll
        for (int d = 0; d < 5; d++) acc[d] = fmaf(v, Wf2[j * 5 + d], acc[d]);
    }
#pragma unroll
    for (int d = 0; d < 5; d++)
        for (int o = 16; o; o >>= 1) acc[d] += __shfl_xor_sync(0xffffffffu, acc[d], o);
    if (lane == 0) {
#pragma unroll
        for (int d = 0; d < 5; d++) g_hA[gw * 5 + d] = acc[d] + bf2[d];
    }
}

__global__ void zero_prop() {
    int i = blockIdx.x * 256 + threadIdx.x;
    if (i < 1000 * 1000) g_prop[i] = 0.f;
}

// edge: val = tanh( relu(P[s]+Qm[d]+br1) . Wr2 + br2 ), scatter-add to prop[s,d]
__global__ void edge_kernel(const int* __restrict__ edges, const float* __restrict__ br1,
                            const float* __restrict__ Wr2, const float* __restrict__ br2, int E) {
    int e = blockIdx.x * 8 + (threadIdx.x >> 5);
    int lane = threadIdx.x & 31;
    if (e >= E) return;
    int s = edges[e];
    int d = edges[E + e];
    const float* Pr = g_P + (size_t)s * 256;
    const float* Qr = g_Qm + (size_t)d * 256;
    float acc = 0.f;
#pragma unroll
    for (int i = 0; i < 8; i++) {
        int j = lane + 32 * i;
        float h = fmaxf(Pr[j] + Qr[j] + br1[j], 0.f);
        acc = fmaf(h, Wr2[j], acc);
    }
    for (int o = 16; o; o >>= 1) acc += __shfl_xor_sync(0xffffffffu, acc, o);
    if (lane == 0) atomicAdd(&g_prop[(size_t)s * 1000 + d], tanhf(acc + br2[0]));
}

// msg[b,n,:] = tanh( sum_m prop[n,m] * hin[b,m,:] )   (320 threads: 64 n x 5 d)
__global__ void msg_kernel(int sel) {
    __shared__ float sp[64][65];
    __shared__ float sh[320];
    const float* hin = sel ? g_hB : g_hA;
    int b = blockIdx.y;
    int n0 = blockIdx.x * 64;
    int tid = threadIdx.x;
    int nl = tid / 5, d = tid % 5;
    float acc = 0.f;
    for (int m0 = 0; m0 < 1000; m0 += 64) {
        int mlen = min(64, 1000 - m0);
        for (int idx = tid; idx < 64 * 64; idx += 320) {
            int r = idx >> 6, c = idx & 63;
            sp[r][c] = (n0 + r < 1000 && c < mlen) ? g_prop[(size_t)(n0 + r) * 1000 + m0 + c] : 0.f;
        }
        sh[tid] = (tid < mlen * 5) ? hin[((size_t)b * 1000 + m0) * 5 + tid] : 0.f;
        __syncthreads();
#pragma unroll 8
        for (int mm = 0; mm < 64; mm++)
            acc = fmaf(sp[nl][mm], sh[mm * 5 + d], acc);
        __syncthreads();
    }
    if (n0 + nl < 1000) g_msg[((size_t)b * 1000 + n0 + nl) * 5 + d] = tanhf(acc);
}

__global__ void gru_kernel(const float* __restrict__ Wih, const float* __restrict__ bih,
                           const float* __restrict__ Whh, const float* __restrict__ bhh, int sel) {
    int r = blockIdx.x * 256 + threadIdx.x;
    if (r >= 16000) return;
    const float* hin = sel ? g_hB : g_hA;
    float* hout = sel ? g_hA : g_hB;
    float x[5], h[5];
#pragma unroll
    for (int d = 0; d < 5; d++) { x[d] = g_msg[r * 5 + d]; h[d] = hin[r * 5 + d]; }
    float out[5];
#pragma unroll
    for (int d = 0; d < 5; d++) {
        float ir = bih[d], iz = bih[5 + d], in = bih[10 + d];
        float hr = bhh[d], hz = bhh[5 + d], hn = bhh[10 + d];
#pragma unroll
        for (int k = 0; k < 5; k++) {
            ir = fmaf(x[k], Wih[d * 5 + k], ir);
            iz = fmaf(x[k], Wih[(5 + d) * 5 + k], iz);
            in = fmaf(x[k], Wih[(10 + d) * 5 + k], in);
            hr = fmaf(h[k], Whh[d * 5 + k], hr);
            hz = fmaf(h[k], Whh[(5 + d) * 5 + k], hz);
            hn = fmaf(h[k], Whh[(10 + d) * 5 + k], hn);
        }
        float rr = 1.f / (1.f + expf(-(ir + hr)));
        float zz = 1.f / (1.f + expf(-(iz + hz)));
        float nn = tanhf(in + rr * hn);
        out[d] = (1.f - zz) * nn + zz * h[d];
    }
#pragma unroll
    for (int d = 0; d < 5; d++) hout[r * 5 + d] = out[d];
}

// logits = relu(h @ Wo1 + bo1) @ Wo2 + bo2  (warp per row, reads g_hB)
__global__ void out_kernel(const float* __restrict__ Wo1, const float* __restrict__ bo1,
                           const float* __restrict__ Wo2, const float* __restrict__ bo2,
                           float* __restrict__ out) {
    int gw = (blockIdx.x * blockDim.x + threadIdx.x) >> 5;
    int lane = threadIdx.x & 31;
    if (gw >= 16000) return;
    float h[5];
#pragma unroll
    for (int d = 0; d < 5; d++) h[d] = g_hB[gw * 5 + d];
    float acc = 0.f;
#pragma unroll
    for (int i = 0; i < 16; i++) {
        int j = lane + 32 * i;
        float t = bo1[j];
#pragma unroll
        for (int d = 0; d < 5; d++) t = fmaf(h[d], Wo1[d * 512 + j], t);
        acc = fmaf(fmaxf(t, 0.f), Wo2[j], acc);
    }
    for (int o = 16; o; o >>= 1) acc += __shfl_xor_sync(0xffffffffu, acc, o);
    if (lane == 0) out[gw] = acc + bo2[0];
}

// ---------------- launcher ----------------
extern "C" void kernel_launch(void* const* d_in, const int* in_sizes, int n_in,
                              void* d_out, int out_size) {
    const float* feats  = (const float*)d_in[0];
    const float* embed  = (const float*)d_in[1];
    const int*   edges  = (const int*)d_in[2];
    const float* W_key  = (const float*)d_in[3];
    const float* b_key  = (const float*)d_in[4];
    const float* W_query= (const float*)d_in[5];
    const float* b_query= (const float*)d_in[6];
    const float* Wf1    = (const float*)d_in[7];
    const float* bf1    = (const float*)d_in[8];
    const float* Wf2    = (const float*)d_in[9];
    const float* bf2    = (const float*)d_in[10];
    const float* Wr1    = (const float*)d_in[11];
    const float* br1    = (const float*)d_in[12];
    const float* Wr2    = (const float*)d_in[13];
    const float* br2    = (const float*)d_in[14];
    const float* Wo1    = (const float*)d_in[15];
    const float* bo1    = (const float*)d_in[16];
    const float* Wo2    = (const float*)d_in[17];
    const float* bo2    = (const float*)d_in[18];
    const float* W_ih   = (const float*)d_in[19];
    const float* b_ih   = (const float*)d_in[20];
    const float* W_hh   = (const float*)d_in[21];
    const float* b_hh   = (const float*)d_in[22];
    const float* W_clf  = (const float*)d_in[23];
    const float* b_clf  = (const float*)d_in[24];

    float* out        = (float*)d_out;
    float* out_logits = out;                       // [16,1000]
    float* out_attn   = out + 16000;               // [16,1000,196]
    float* out_img    = out + 16000 + 16 * 1000 * 196;  // [16,1000]

    int E = in_sizes[2] / 2;

    float *p_keysfk, *p_WB, *p_biasB, *p_queries, *p_kT, *p_scores, *p_H1, *p_P, *p_Qm;
    cudaGetSymbolAddress((void**)&p_keysfk, g_keysfk);
    cudaGetSymbolAddress((void**)&p_WB, g_WB);
    cudaGetSymbolAddress((void**)&p_biasB, g_biasB);
    cudaGetSymbolAddress((void**)&p_queries, g_queries);
    cudaGetSymbolAddress((void**)&p_kT, g_kT);
    cudaGetSymbolAddress((void**)&p_scores, g_scores);
    cudaGetSymbolAddress((void**)&p_H1, g_H1);
    cudaGetSymbolAddress((void**)&p_P, g_P);
    cudaGetSymbolAddress((void**)&p_Qm, g_Qm);

    // ---- imagenet branch ----
    pooled_kernel<<<dim3(8, 16), 256>>>(feats);
    clf_kernel<<<dim3(8, 16), 128>>>(W_clf, b_clf, out_img);
    softmax1000<<<16, 256>>>(out_img);

    // ---- fused feats GEMM: [keys | FK] = feats @ [W_key | Wf1] (+[b_key|0]) ----
    packB<<<8192, 256>>>(W_key, b_key, Wf1);
    sgemm_db<<<dim3(8, 25, 1), 256>>>(feats, 2048, 0, p_WB, 1024, 0, p_biasB,
                                      p_keysfk, 1024, 0, 3136, 1024, 2048, 0);

    // ---- queries = embed @ W_query + b_query ----
    sgemm_db<<<dim3(4, 8, 1), 256>>>(embed, 300, 0, W_query, 512, 0, b_query,
                                     p_queries, 512, 0, 1000, 512, 300, 0);

    // ---- scores = queries @ keys^T (per b), via kT ----
    transpose_keys<<<dim3(7, 16, 16), dim3(32, 8)>>>();
    sgemm_db<<<dim3(2, 8, 16), 256>>>(p_queries, 512, 0, p_kT, 196, (long long)512 * 196,
                                      nullptr, p_scores, 196, (long long)1000 * 196,
                                      1000, 196, 512, 0);
    softmax196<<<2000, 256>>>(out_attn);

    // ---- hidden1 = relu(attn @ FK + bf1); h0 = hidden1 @ Wf2 + bf2 ----
    sgemm_db<<<dim3(4, 8, 16), 256>>>(out_attn, 196, (long long)1000 * 196,
                                      p_keysfk + 512, 1024, (long long)196 * 1024, bf1,
                                      p_H1, 512, (long long)1000 * 512,
                                      1000, 512, 196, 1);
    h0_kernel<<<2000, 256>>>(Wf2, bf2);

    // ---- edge weights: P/Qm precompute + per-edge finish + scatter ----
    sgemm_db<<<dim3(2, 8, 1), 256>>>(embed, 300, 0, Wr1, 256, 0, nullptr,
                                     p_P, 256, 0, 1000, 256, 300, 0);
    sgemm_db<<<dim3(2, 8, 1), 256>>>(embed, 300, 0, Wr1 + 300 * 256, 256, 0, nullptr,
                                     p_Qm, 256, 0, 1000, 256, 300, 0);
    zero_prop<<<3907, 256>>>();
    edge_kernel<<<(E + 7) / 8, 256>>>(edges, br1, Wr2, br2, E);

    // ---- 5 message-passing + GRU steps (ping-pong g_hA/g_hB) ----
    for (int t = 0; t < TMAXq; t++) {
        int sel = t & 1;   // 0: read hA write hB ; 1: read hB write hA
        msg_kernel<<<dim3(16, 16), 320>>>(sel);
        gru_kernel<<<63, 256>>>(W_ih, b_ih, W_hh, b_hh, sel);
    }

    // final hidden lives in g_hB after 5 steps
    out_kernel<<<2000, 256>>>(Wo1, bo1, Wo2, bo2, out_logits);

    (void)n_in; (void)out_size;
}

// round 3
// speedup vs baseline: 1.1546x; 1.0487x over previous
#include <cuda_runtime.h>
#include <math.h>

// ---------------- problem dims ----------------
#define Bq 16
#define Lq 196
#define FDq 2048
#define Nq 1000
#define WDq 300
#define HDq 512
#define DDq 5
#define NIMGq 1000
#define TMAXq 5

// ---------------- device scratch ----------------
__device__ __align__(256) float g_keysfk[3136 * 1024];   // [B*L,1024]: 0..511 keys, 512..1023 FK
__device__ __align__(256) float g_WB[2048 * 1024];       // packed [W_key | Wf1]
__device__ __align__(256) float g_biasB[1024];           // [b_key | 0]
__device__ __align__(256) float g_Wr1p[300 * 512];       // packed [Wr1_top | Wr1_bot]
__device__ __align__(256) float g_queries[1000 * 512];
__device__ __align__(256) float g_kT[16 * 512 * 196];
__device__ __align__(256) float g_scores[16 * 1000 * 196];
__device__ __align__(256) float g_H1[16000 * 512];
__device__ __align__(256) float g_PQ[1000 * 512];        // cols 0..255 P, 256..511 Qm
__device__ __align__(256) float g_prop[1000 * 1000];
__device__ __align__(256) float g_hA[16000 * 5];
__device__ __align__(256) float g_hB[16000 * 5];
__device__ __align__(256) float g_pooled[16 * 2048];

// ---------------- double-buffered SGEMM with packed f32x2 FMA ----------------
// 128x128 tile, BK=16, 256 threads, 8x8 microtile (as 8x4 f32x2 pairs).
__global__ __launch_bounds__(256, 2) void sgemm_db(
    const float* __restrict__ A, int lda, long long sA,
    const float* __restrict__ B, int ldb, long long sB,
    const float* __restrict__ bias,
    float* __restrict__ C, int ldc, long long sC,
    int M, int N, int K, int do_relu)
{
    __shared__ float As[2][16][128];
    __shared__ float Bs[2][16][128];
    int z = blockIdx.z;
    A += (size_t)z * sA; B += (size_t)z * sB; C += (size_t)z * sC;
    int tid = threadIdx.x;
    int brow = blockIdx.y * 128;
    int bcol = blockIdx.x * 128;

    int a_row = tid >> 1;              // 0..127
    int a_col = (tid & 1) * 8;         // 0 or 8
    int b_k   = tid >> 4;              // 0..15
    int b_col = (tid & 15) * 8;        // 0..120
    int ty = tid >> 4, tx = tid & 15;

    unsigned long long acc2[8][4];
#pragma unroll
    for (int i = 0; i < 8; i++)
#pragma unroll
        for (int j = 0; j < 4; j++) acc2[i][j] = 0ULL;

    int nk = (K + 15) >> 4;
    float4 pa0, pa1, pb0, pb1;

    // preload tile 0
    {
        pa0 = make_float4(0.f,0.f,0.f,0.f); pa1 = pa0; pb0 = pa0; pb1 = pa0;
        if (brow + a_row < M) {
            const float* p = A + (size_t)(brow + a_row) * lda + a_col;
            if (a_col < K)     pa0 = *reinterpret_cast<const float4*>(p);
            if (a_col + 4 < K) pa1 = *reinterpret_cast<const float4*>(p + 4);
        }
        if (b_k < K) {
            const float* p = B + (size_t)b_k * ldb + bcol + b_col;
            if (bcol + b_col < N)     pb0 = *reinterpret_cast<const float4*>(p);
            if (bcol + b_col + 4 < N) pb1 = *reinterpret_cast<const float4*>(p + 4);
        }
        As[0][a_col+0][a_row] = pa0.x; As[0][a_col+1][a_row] = pa0.y;
        As[0][a_col+2][a_row] = pa0.z; As[0][a_col+3][a_row] = pa0.w;
        As[0][a_col+4][a_row] = pa1.x; As[0][a_col+5][a_row] = pa1.y;
        As[0][a_col+6][a_row] = pa1.z; As[0][a_col+7][a_row] = pa1.w;
        *reinterpret_cast<float4*>(&Bs[0][b_k][b_col])     = pb0;
        *reinterpret_cast<float4*>(&Bs[0][b_k][b_col + 4]) = pb1;
    }
    __syncthreads();

    for (int t = 0; t < nk; t++) {
        int buf = t & 1;
        int nxt = t + 1;
        if (nxt < nk) {
            int k0 = nxt << 4;
            pa0 = make_float4(0.f,0.f,0.f,0.f); pa1 = pa0; pb0 = pa0; pb1 = pa0;
            if (brow + a_row < M) {
                const float* p = A + (size_t)(brow + a_row) * lda + k0 + a_col;
                if (k0 + a_col < K)     pa0 = *reinterpret_cast<const float4*>(p);
                if (k0 + a_col + 4 < K) pa1 = *reinterpret_cast<const float4*>(p + 4);
            }
            if (k0 + b_k < K) {
                const float* p = B + (size_t)(k0 + b_k) * ldb + bcol + b_col;
                if (bcol + b_col < N)     pb0 = *reinterpret_cast<const float4*>(p);
                if (bcol + b_col + 4 < N) pb1 = *reinterpret_cast<const float4*>(p + 4);
            }
        }

#pragma unroll
        for (int kk = 0; kk < 16; kk++) {
            float4 a0 = *reinterpret_cast<const float4*>(&As[buf][kk][ty * 8]);
            float4 a1 = *reinterpret_cast<const float4*>(&As[buf][kk][ty * 8 + 4]);
            ulonglong2 bq0 = *reinterpret_cast<const ulonglong2*>(&Bs[buf][kk][tx * 8]);
            ulonglong2 bq1 = *reinterpret_cast<const ulonglong2*>(&Bs[buf][kk][tx * 8 + 4]);
            unsigned long long bb0 = bq0.x, bb1 = bq0.y, bb2 = bq1.x, bb3 = bq1.y;
            float av[8] = {a0.x, a0.y, a0.z, a0.w, a1.x, a1.y, a1.z, a1.w};
#pragma unroll
            for (int i = 0; i < 8; i++) {
                unsigned long long aa;
                unsigned int ab = __float_as_uint(av[i]);
                asm("mov.b64 %0, {%1, %1};" : "=l"(aa) : "r"(ab));
                asm("fma.rn.f32x2 %0, %1, %2, %0;" : "+l"(acc2[i][0]) : "l"(aa), "l"(bb0));
                asm("fma.rn.f32x2 %0, %1, %2, %0;" : "+l"(acc2[i][1]) : "l"(aa), "l"(bb1));
                asm("fma.rn.f32x2 %0, %1, %2, %0;" : "+l"(acc2[i][2]) : "l"(aa), "l"(bb2));
                asm("fma.rn.f32x2 %0, %1, %2, %0;" : "+l"(acc2[i][3]) : "l"(aa), "l"(bb3));
            }
        }

        if (nxt < nk) {
            int nb = nxt & 1;
            As[nb][a_col+0][a_row] = pa0.x; As[nb][a_col+1][a_row] = pa0.y;
            As[nb][a_col+2][a_row] = pa0.z; As[nb][a_col+3][a_row] = pa0.w;
            As[nb][a_col+4][a_row] = pa1.x; As[nb][a_col+5][a_row] = pa1.y;
            As[nb][a_col+6][a_row] = pa1.z; As[nb][a_col+7][a_row] = pa1.w;
            *reinterpret_cast<float4*>(&Bs[nb][b_k][b_col])     = pb0;
            *reinterpret_cast<float4*>(&Bs[nb][b_k][b_col + 4]) = pb1;
        }
        __syncthreads();
    }

#pragma unroll
    for (int i = 0; i < 8; i++) {
        int r = brow + ty * 8 + i;
        if (r >= M) continue;
#pragma unroll
        for (int j = 0; j < 4; j++) {
            unsigned long long v = acc2[i][j];
            float c0 = __uint_as_float((unsigned int)v);
            float c1 = __uint_as_float((unsigned int)(v >> 32));
            int c = bcol + tx * 8 + j * 2;
            if (c < N) {
                float t = c0;
                if (bias) t += bias[c];
                if (do_relu) t = fmaxf(t, 0.f);
                C[(size_t)r * ldc + c] = t;
            }
            if (c + 1 < N) {
                float t = c1;
                if (bias) t += bias[c + 1];
                if (do_relu) t = fmaxf(t, 0.f);
                C[(size_t)r * ldc + c + 1] = t;
            }
        }
    }
}

// ---------------- small kernels ----------------
__global__ void pooled_kernel(const float* __restrict__ feats) {
    int f = blockIdx.x * 256 + threadIdx.x;
    int b = blockIdx.y;
    const float* p = feats + (size_t)b * Lq * FDq + f;
    float s = 0.f;
#pragma unroll 4
    for (int l = 0; l < Lq; l++) s += p[(size_t)l * FDq];
    g_pooled[b * FDq + f] = s * (1.f / (float)Lq);
}

__global__ void clf_kernel(const float* __restrict__ W_clf, const float* __restrict__ b_clf,
                           float* __restrict__ out_img) {
    __shared__ float sp[2048];
    int b = blockIdx.y;
    for (int i = threadIdx.x; i < 2048; i += 128) sp[i] = g_pooled[b * 2048 + i];
    __syncthreads();
    int c = blockIdx.x * 128 + threadIdx.x;
    if (c >= NIMGq) return;
    float acc = b_clf[c];
#pragma unroll 8
    for (int f = 0; f < 2048; f++) acc = fmaf(sp[f], W_clf[(size_t)f * NIMGq + c], acc);
    out_img[b * NIMGq + c] = acc;
}

__global__ void softmax1000(float* __restrict__ base) {
    __shared__ float sv[1000];
    __shared__ float red[8];
    int b = blockIdx.x, tid = threadIdx.x;
    float* row = base + (size_t)b * 1000;
    float m = -1e30f;
    for (int i = tid; i < 1000; i += 256) { float x = row[i]; sv[i] = x; m = fmaxf(m, x); }
    for (int o = 16; o; o >>= 1) m = fmaxf(m, __shfl_xor_sync(0xffffffffu, m, o));
    if ((tid & 31) == 0) red[tid >> 5] = m;
    __syncthreads();
    float bm = red[0];
#pragma unroll
    for (int i = 1; i < 8; i++) bm = fmaxf(bm, red[i]);
    float s = 0.f;
    for (int i = tid; i < 1000; i += 256) { float e = expf(sv[i] - bm); sv[i] = e; s += e; }
    for (int o = 16; o; o >>= 1) s += __shfl_xor_sync(0xffffffffu, s, o);
    __syncthreads();
    if ((tid & 31) == 0) red[tid >> 5] = s;
    __syncthreads();
    float bs = 0.f;
#pragma unroll
    for (int i = 0; i < 8; i++) bs += red[i];
    float inv = 1.f / bs;
    for (int i = tid; i < 1000; i += 256) row[i] = sv[i] * inv;
}

// packs [W_key|Wf1] -> g_WB, [b_key|0] -> g_biasB, [Wr1_top|Wr1_bot] -> g_Wr1p
__global__ void packB(const float* __restrict__ Wk, const float* __restrict__ bk,
                      const float* __restrict__ Wf1, const float* __restrict__ Wr1) {
    int idx = blockIdx.x * 256 + threadIdx.x;
    if (idx < 2048 * 1024) {
        int k = idx >> 10, j = idx & 1023;
        g_WB[idx] = (j < 512) ? Wk[k * 512 + j] : Wf1[k * 512 + j - 512];
    }
    if (idx < 1024) g_biasB[idx] = (idx < 512) ? bk[idx] : 0.f;
    if (idx < 300 * 512) {
        int k = idx >> 9, j = idx & 511;
        g_Wr1p[idx] = (j < 256) ? Wr1[k * 256 + j] : Wr1[(300 + k) * 256 + j - 256];
    }
}

__global__ void transpose_keys() {
    __shared__ float tile[32][33];
    int b = blockIdx.z;
    int l0 = blockIdx.x * 32, h0 = blockIdx.y * 32;
    int tx = threadIdx.x, ty = threadIdx.y;
#pragma unroll
    for (int i = 0; i < 32; i += 8) {
        int l = l0 + i + ty;
        tile[i + ty][tx] = (l < Lq) ? g_keysfk[((size_t)b * Lq + l) * 1024 + h0 + tx] : 0.f;
    }
    __syncthreads();
#pragma unroll
    for (int i = 0; i < 32; i += 8) {
        int h = h0 + i + ty;
        int l = l0 + tx;
        if (l < Lq) g_kT[((size_t)b * 512 + h) * Lq + l] = tile[tx][i + ty];
    }
}

__global__ void softmax196(float* __restrict__ attn) {
    int gw = (blockIdx.x * blockDim.x + threadIdx.x) >> 5;
    int lane = threadIdx.x & 31;
    if (gw >= Bq * Nq) return;
    const float* src = g_scores + (size_t)gw * Lq;
    float v[7];
    float m = -1e30f;
#pragma unroll
    for (int i = 0; i < 7; i++) {
        int j = lane + 32 * i;
        v[i] = (j < Lq) ? src[j] : -1e30f;
        m = fmaxf(m, v[i]);
    }
    for (int o = 16; o; o >>= 1) m = fmaxf(m, __shfl_xor_sync(0xffffffffu, m, o));
    float s = 0.f;
#pragma unroll
    for (int i = 0; i < 7; i++) {
        int j = lane + 32 * i;
        v[i] = (j < Lq) ? expf(v[i] - m) : 0.f;
        s += v[i];
    }
    for (int o = 16; o; o >>= 1) s += __shfl_xor_sync(0xffffffffu, s, o);
    float inv = 1.f / s;
#pragma unroll
    for (int i = 0; i < 7; i++) {
        int j = lane + 32 * i;
        if (j < Lq) attn[(size_t)gw * Lq + j] = v[i] * inv;
    }
}

__global__ void h0_kernel(const float* __restrict__ Wf2, const float* __restrict__ bf2) {
    int gw = (blockIdx.x * blockDim.x + threadIdx.x) >> 5;
    int lane = threadIdx.x & 31;
    if (gw >= 16000) return;
    const float* row = g_H1 + (size_t)gw * 512;
    float acc[5] = {0.f, 0.f, 0.f, 0.f, 0.f};
#pragma unroll
    for (int i = 0; i < 16; i++) {
        int j = lane + 32 * i;
        float v = row[j];
#pragma unroll
        for (int d = 0; d < 5; d++) acc[d] = fmaf(v, Wf2[j * 5 + d], acc[d]);
    }
#pragma unroll
    for (int d = 0; d < 5; d++)
        for (int o = 16; o; o >>= 1) acc[d] += __shfl_xor_sync(0xffffffffu, acc[d], o);
    if (lane == 0) {
#pragma unroll
        for (int d = 0; d < 5; d++) g_hA[gw * 5 + d] = acc[d] + bf2[d];
    }
}

__global__ void zero_prop() {
    int i = blockIdx.x * 256 + threadIdx.x;
    if (i < 1000 * 1000) g_prop[i] = 0.f;
}

__global__ void edge_kernel(const int* __restrict__ edges, const float* __restrict__ br1,
                            const float* __restrict__ Wr2, const float* __restrict__ br2, int E) {
    int e = blockIdx.x * 8 + (threadIdx.x >> 5);
    int lane = threadIdx.x & 31;
    if (e >= E) return;
    int s = edges[e];
    int d = edges[E + e];
    const float* Pr = g_PQ + (size_t)s * 512;
    const float* Qr = g_PQ + (size_t)d * 512 + 256;
    float acc = 0.f;
#pragma unroll
    for (int i = 0; i < 8; i++) {
        int j = lane + 32 * i;
        float h = fmaxf(Pr[j] + Qr[j] + br1[j], 0.f);
        acc = fmaf(h, Wr2[j], acc);
    }
    for (int o = 16; o; o >>= 1) acc += __shfl_xor_sync(0xffffffffu, acc, o);
    if (lane == 0) atomicAdd(&g_prop[(size_t)s * 1000 + d], tanhf(acc + br2[0]));
}

// fused: msg = tanh(prop @ h_in) then GRU -> h_out   (320 threads: 64 n x 5 d)
__global__ void msg_gru_kernel(const float* __restrict__ Wih, const float* __restrict__ bih,
                               const float* __restrict__ Whh, const float* __restrict__ bhh,
                               int sel) {
    __shared__ float sp[64][65];
    __shared__ float sh[320];
    __shared__ float sx[64][5];
    const float* hin = sel ? g_hB : g_hA;
    float* hout = sel ? g_hA : g_hB;
    int b = blockIdx.y;
    int n0 = blockIdx.x * 64;
    int tid = threadIdx.x;
    int nl = tid / 5, d = tid % 5;
    float acc = 0.f;
    for (int m0 = 0; m0 < 1000; m0 += 64) {
        int mlen = min(64, 1000 - m0);
        for (int idx = tid; idx < 64 * 64; idx += 320) {
            int r = idx >> 6, c = idx & 63;
            sp[r][c] = (n0 + r < 1000 && c < mlen) ? g_prop[(size_t)(n0 + r) * 1000 + m0 + c] : 0.f;
        }
        sh[tid] = (tid < mlen * 5) ? hin[((size_t)b * 1000 + m0) * 5 + tid] : 0.f;
        __syncthreads();
#pragma unroll 8
        for (int mm = 0; mm < 64; mm++)
            acc = fmaf(sp[nl][mm], sh[mm * 5 + d], acc);
        __syncthreads();
    }
    sx[nl][d] = tanhf(acc);
    __syncthreads();

    int n = n0 + nl;
    if (n >= 1000) return;
    size_t roff = ((size_t)b * 1000 + n) * 5;
    float x[5], h[5];
#pragma unroll
    for (int k = 0; k < 5; k++) { x[k] = sx[nl][k]; h[k] = hin[roff + k]; }
    float ir = bih[d], iz = bih[5 + d], in_ = bih[10 + d];
    float hr = bhh[d], hz = bhh[5 + d], hn = bhh[10 + d];
#pragma unroll
    for (int k = 0; k < 5; k++) {
        ir = fmaf(x[k], Wih[d * 5 + k], ir);
        iz = fmaf(x[k], Wih[(5 + d) * 5 + k], iz);
        in_ = fmaf(x[k], Wih[(10 + d) * 5 + k], in_);
        hr = fmaf(h[k], Whh[d * 5 + k], hr);
        hz = fmaf(h[k], Whh[(5 + d) * 5 + k], hz);
        hn = fmaf(h[k], Whh[(10 + d) * 5 + k], hn);
    }
    float rr = 1.f / (1.f + expf(-(ir + hr)));
    float zz = 1.f / (1.f + expf(-(iz + hz)));
    float nn = tanhf(in_ + rr * hn);
    hout[roff + d] = (1.f - zz) * nn + zz * h[d];
}

__global__ void out_kernel(const float* __restrict__ Wo1, const float* __restrict__ bo1,
                           const float* __restrict__ Wo2, const float* __restrict__ bo2,
                           float* __restrict__ out) {
    int gw = (blockIdx.x * blockDim.x + threadIdx.x) >> 5;
    int lane = threadIdx.x & 31;
    if (gw >= 16000) return;
    float h[5];
#pragma unroll
    for (int d = 0; d < 5; d++) h[d] = g_hB[gw * 5 + d];
    float acc = 0.f;
#pragma unroll
    for (int i = 0; i < 16; i++) {
        int j = lane + 32 * i;
        float t = bo1[j];
#pragma unroll
        for (int d = 0; d < 5; d++) t = fmaf(h[d], Wo1[d * 512 + j], t);
        acc = fmaf(fmaxf(t, 0.f), Wo2[j], acc);
    }
    for (int o = 16; o; o >>= 1) acc += __shfl_xor_sync(0xffffffffu, acc, o);
    if (lane == 0) out[gw] = acc + bo2[0];
}

// ---------------- launcher ----------------
extern "C" void kernel_launch(void* const* d_in, const int* in_sizes, int n_in,
                              void* d_out, int out_size) {
    const float* feats  = (const float*)d_in[0];
    const float* embed  = (const float*)d_in[1];
    const int*   edges  = (const int*)d_in[2];
    const float* W_key  = (const float*)d_in[3];
    const float* b_key  = (const float*)d_in[4];
    const float* W_query= (const float*)d_in[5];
    const float* b_query= (const float*)d_in[6];
    const float* Wf1    = (const float*)d_in[7];
    const float* bf1    = (const float*)d_in[8];
    const float* Wf2    = (const float*)d_in[9];
    const float* bf2    = (const float*)d_in[10];
    const float* Wr1    = (const float*)d_in[11];
    const float* br1    = (const float*)d_in[12];
    const float* Wr2    = (const float*)d_in[13];
    const float* br2    = (const float*)d_in[14];
    const float* Wo1    = (const float*)d_in[15];
    const float* bo1    = (const float*)d_in[16];
    const float* Wo2    = (const float*)d_in[17];
    const float* bo2    = (const float*)d_in[18];
    const float* W_ih   = (const float*)d_in[19];
    const float* b_ih   = (const float*)d_in[20];
    const float* W_hh   = (const float*)d_in[21];
    const float* b_hh   = (const float*)d_in[22];
    const float* W_clf  = (const float*)d_in[23];
    const float* b_clf  = (const float*)d_in[24];

    float* out        = (float*)d_out;
    float* out_logits = out;
    float* out_attn   = out + 16000;
    float* out_img    = out + 16000 + 16 * 1000 * 196;

    int E = in_sizes[2] / 2;

    float *p_keysfk, *p_WB, *p_biasB, *p_Wr1p, *p_queries, *p_kT, *p_scores, *p_H1, *p_PQ;
    cudaGetSymbolAddress((void**)&p_keysfk, g_keysfk);
    cudaGetSymbolAddress((void**)&p_WB, g_WB);
    cudaGetSymbolAddress((void**)&p_biasB, g_biasB);
    cudaGetSymbolAddress((void**)&p_Wr1p, g_Wr1p);
    cudaGetSymbolAddress((void**)&p_queries, g_queries);
    cudaGetSymbolAddress((void**)&p_kT, g_kT);
    cudaGetSymbolAddress((void**)&p_scores, g_scores);
    cudaGetSymbolAddress((void**)&p_H1, g_H1);
    cudaGetSymbolAddress((void**)&p_PQ, g_PQ);

    // ---- imagenet branch ----
    pooled_kernel<<<dim3(8, 16), 256>>>(feats);
    clf_kernel<<<dim3(8, 16), 128>>>(W_clf, b_clf, out_img);
    softmax1000<<<16, 256>>>(out_img);

    // ---- fused feats GEMM: [keys | FK] = feats @ [W_key | Wf1] ----
    packB<<<8192, 256>>>(W_key, b_key, Wf1, Wr1);
    sgemm_db<<<dim3(8, 25, 1), 256>>>(feats, 2048, 0, p_WB, 1024, 0, p_biasB,
                                      p_keysfk, 1024, 0, 3136, 1024, 2048, 0);

    // ---- queries = embed @ W_query + b_query ----
    sgemm_db<<<dim3(4, 8, 1), 256>>>(embed, 300, 0, W_query, 512, 0, b_query,
                                     p_queries, 512, 0, 1000, 512, 300, 0);

    // ---- scores = queries @ keys^T (per b) ----
    transpose_keys<<<dim3(7, 16, 16), dim3(32, 8)>>>();
    sgemm_db<<<dim3(2, 8, 16), 256>>>(p_queries, 512, 0, p_kT, 196, (long long)512 * 196,
                                      nullptr, p_scores, 196, (long long)1000 * 196,
                                      1000, 196, 512, 0);
    softmax196<<<2000, 256>>>(out_attn);

    // ---- hidden1 = relu(attn @ FK + bf1); h0 = hidden1 @ Wf2 + bf2 ----
    sgemm_db<<<dim3(4, 8, 16), 256>>>(out_attn, 196, (long long)1000 * 196,
                                      p_keysfk + 512, 1024, (long long)196 * 1024, bf1,
                                      p_H1, 512, (long long)1000 * 512,
                                      1000, 512, 196, 1);
    h0_kernel<<<2000, 256>>>(Wf2, bf2);

    // ---- edge weights: [P|Qm] = embed @ Wr1p, per-edge finish + scatter ----
    sgemm_db<<<dim3(4, 8, 1), 256>>>(embed, 300, 0, p_Wr1p, 512, 0, nullptr,
                                     p_PQ, 512, 0, 1000, 512, 300, 0);
    zero_prop<<<3907, 256>>>();
    edge_kernel<<<(E + 7) / 8, 256>>>(edges, br1, Wr2, br2, E);

    // ---- 5 fused message-passing + GRU steps (ping-pong g_hA/g_hB) ----
    for (int t = 0; t < TMAXq; t++) {
        int sel = t & 1;
        msg_gru_kernel<<<dim3(16, 16), 320>>>(W_ih, b_ih, W_hh, b_hh, sel);
    }

    out_kernel<<<2000, 256>>>(Wo1, bo1, Wo2, bo2, out_logits);

    (void)n_in; (void)out_size;
}